// round 2
// baseline (speedup 1.0000x reference)
#include <cuda_runtime.h>

#define NTOK   4096
#define DMODEL 2048
#define NH     16
#define HDIM   128
#define SDIM   64
#define NSLOT  16
#define NUNIT  (NTOK * NH)

#define OUT_STACK_OFF 8388608ll
#define OUT_MASK_OFF  75497472ll

__device__ float g_part[8ll * NTOK * 48];
__device__ float g_act[(size_t)NTOK * 48];
__device__ float g_k[(size_t)NUNIT * SDIM];
__device__ float g_mo[(size_t)NUNIT * SDIM];

// ---- Kernel 1: logits partials (split-K). grid = 64 token-tiles * 8 ksplits.
__global__ void __launch_bounds__(256) k_logits(const float* __restrict__ hid,
                                                const float* __restrict__ Wa) {
    const int tile = blockIdx.x >> 3;
    const int ks   = blockIdx.x & 7;
    const int t0   = tile * 64;
    const int kb   = ks * 256;
    __shared__ float a_sm[64 * 65];
    __shared__ float w_sm[48 * 65];
    const int tid = threadIdx.x;
    const int tg  = tid & 15;
    const int og  = tid >> 4;
    float acc[4][3];
#pragma unroll
    for (int i = 0; i < 4; i++)
#pragma unroll
        for (int j = 0; j < 3; j++) acc[i][j] = 0.f;

    for (int kc = 0; kc < 256; kc += 64) {
        __syncthreads();
        for (int i = tid; i < 64 * 64; i += 256) {
            int t = i >> 6, kk = i & 63;
            a_sm[t * 65 + kk] = hid[(size_t)(t0 + t) * DMODEL + kb + kc + kk];
        }
        for (int i = tid; i < 48 * 64; i += 256) {
            int o = i >> 6, kk = i & 63;
            w_sm[o * 65 + kk] = Wa[(size_t)o * DMODEL + kb + kc + kk];
        }
        __syncthreads();
#pragma unroll 4
        for (int kk = 0; kk < 64; kk++) {
            float av[4], wv[3];
#pragma unroll
            for (int tt = 0; tt < 4; tt++) av[tt] = a_sm[(tg + 16 * tt) * 65 + kk];
#pragma unroll
            for (int oc = 0; oc < 3; oc++) wv[oc] = w_sm[(og * 3 + oc) * 65 + kk];
#pragma unroll
            for (int tt = 0; tt < 4; tt++)
#pragma unroll
                for (int oc = 0; oc < 3; oc++)
                    acc[tt][oc] = fmaf(av[tt], wv[oc], acc[tt][oc]);
        }
    }
#pragma unroll
    for (int tt = 0; tt < 4; tt++)
#pragma unroll
        for (int oc = 0; oc < 3; oc++)
            g_part[((size_t)ks * NTOK + t0 + tg + 16 * tt) * 48 + og * 3 + oc] =
                acc[tt][oc];
}

// ---- Kernel 2: reduce partials, softmax over 3 actions.
__global__ void __launch_bounds__(256) k_actsm() {
    const int gid = blockIdx.x * 256 + threadIdx.x;  // 0..65535
    const int t = gid >> 4, h = gid & 15;
    float l0 = 0.f, l1 = 0.f, l2 = 0.f;
#pragma unroll
    for (int ks = 0; ks < 8; ks++) {
        size_t b = ((size_t)ks * NTOK + t) * 48 + h * 3;
        l0 += g_part[b]; l1 += g_part[b + 1]; l2 += g_part[b + 2];
    }
    const float s = 0.08838834764831845f;  // 1/sqrt(128)
    l0 *= s; l1 *= s; l2 *= s;
    float m = fmaxf(l0, fmaxf(l1, l2));
    float e0 = __expf(l0 - m), e1 = __expf(l1 - m), e2 = __expf(l2 - m);
    float inv = 1.f / (e0 + e1 + e2);
    size_t ob = (size_t)t * 48 + h * 3;
    g_act[ob] = e0 * inv; g_act[ob + 1] = e1 * inv; g_act[ob + 2] = e2 * inv;
}

// ---- Kernel 3: k = hidden([65536 x 128]) @ W_down^T -> [65536 x 64].
__global__ void __launch_bounds__(256) k_down(const float* __restrict__ hid,
                                              const float* __restrict__ Wd) {
    const int u0 = blockIdx.x * 128;
    __shared__ float a_sm[128 * 33];
    __shared__ float w_sm[64 * 33];
    const int tid = threadIdx.x;
    const int rg = tid & 15;
    const int cg = tid >> 4;
    float acc[8][4];
#pragma unroll
    for (int i = 0; i < 8; i++)
#pragma unroll
        for (int j = 0; j < 4; j++) acc[i][j] = 0.f;

    for (int kc = 0; kc < 128; kc += 32) {
        __syncthreads();
        for (int i = tid; i < 128 * 32; i += 256) {
            int r = i >> 5, kk = i & 31;
            a_sm[r * 33 + kk] = hid[(size_t)(u0 + r) * HDIM + kc + kk];
        }
        for (int i = tid; i < 64 * 32; i += 256) {
            int c = i >> 5, kk = i & 31;
            w_sm[c * 33 + kk] = Wd[(size_t)c * HDIM + kc + kk];
        }
        __syncthreads();
#pragma unroll 4
        for (int kk = 0; kk < 32; kk++) {
            float av[8], wv[4];
#pragma unroll
            for (int rr = 0; rr < 8; rr++) av[rr] = a_sm[(rg + 16 * rr) * 33 + kk];
#pragma unroll
            for (int cc = 0; cc < 4; cc++) wv[cc] = w_sm[(cg * 4 + cc) * 33 + kk];
#pragma unroll
            for (int rr = 0; rr < 8; rr++)
#pragma unroll
                for (int cc = 0; cc < 4; cc++)
                    acc[rr][cc] = fmaf(av[rr], wv[cc], acc[rr][cc]);
        }
    }
#pragma unroll
    for (int rr = 0; rr < 8; rr++) {
        float4 v = make_float4(acc[rr][0], acc[rr][1], acc[rr][2], acc[rr][3]);
        *(float4*)&g_k[(size_t)(u0 + rg + 16 * rr) * SDIM + cg * 4] = v;
    }
}

// ---- Kernel 4: stack blend + masked gate softmax + memory_output scratch.
__global__ void __launch_bounds__(256) k_stack(const float* __restrict__ stk,
                                               const float* __restrict__ msk,
                                               const float* __restrict__ Wg,
                                               float* __restrict__ out) {
    const int tid = threadIdx.x;
    const int uu  = tid >> 6;
    const int d   = tid & 63;
    const int u   = blockIdx.x * 4 + uu;
    const int t   = u >> 4, h = u & 15;
    __shared__ float msm[4][16];
    __shared__ float red[4][2][17];
    if (d < 16) msm[uu][d] = msk[(size_t)u * 16 + d];
    const float* sp = stk + (size_t)u * (NSLOT * SDIM);
    float st[16];
#pragma unroll
    for (int j = 0; j < 16; j++) st[j] = sp[j * 64 + d];
    size_t ab = (size_t)t * 48 + h * 3;
    float ap = g_act[ab], apop = g_act[ab + 1], an = g_act[ab + 2];
    float kd = g_k[(size_t)u * 64 + d];
    __syncthreads();

    float nw[16];
    nw[0] = ap * kd + apop * st[1] + an * st[0];
#pragma unroll
    for (int j = 1; j < 15; j++)
        nw[j] = ap * st[j - 1] + apop * st[j + 1] + an * st[j];
    nw[15] = ap * st[14] + an * st[15];

    float* ns = out + OUT_STACK_OFF + (size_t)u * (NSLOT * SDIM);
#pragma unroll
    for (int j = 0; j < 16; j++) ns[j * 64 + d] = nw[j];

    float mk[16];
#pragma unroll
    for (int j = 0; j < 16; j++) {
        float pm = (j == 0) ? 1.f : msm[uu][j - 1];
        float qm = (j < 15) ? msm[uu][j + 1] : 0.f;
        mk[j] = ap * pm + apop * qm + an * msm[uu][j];
    }
    if (d < 16) out[OUT_MASK_OFF + (size_t)u * 16 + d] = mk[d];

    float gd = Wg[d];
    const int wh   = (tid >> 5) & 1;
    const int lane = tid & 31;
#pragma unroll
    for (int j = 0; j < 16; j++) {
        float v = nw[j] * gd;
        v += __shfl_xor_sync(0xffffffffu, v, 16);
        v += __shfl_xor_sync(0xffffffffu, v, 8);
        v += __shfl_xor_sync(0xffffffffu, v, 4);
        v += __shfl_xor_sync(0xffffffffu, v, 2);
        v += __shfl_xor_sync(0xffffffffu, v, 1);
        if (lane == 0) red[uu][wh][j] = v;
    }
    __syncthreads();

    float sc[16], mx = -3.4e38f;
#pragma unroll
    for (int j = 0; j < 16; j++) {
        sc[j] = red[uu][0][j] + red[uu][1][j] + (1.f - mk[j]) * (-1e9f);
        mx = fmaxf(mx, sc[j]);
    }
    float ssum = 0.f;
#pragma unroll
    for (int j = 0; j < 16; j++) { sc[j] = __expf(sc[j] - mx); ssum += sc[j]; }
    float inv = 1.f / ssum;
    float mo = 0.f;
#pragma unroll
    for (int j = 0; j < 16; j++) mo += nw[j] * sc[j];
    g_mo[(size_t)u * 64 + d] = mo * inv;
}

// ---- Kernel 5: out = res_weight * (mo @ W_up^T) + hidden.
__global__ void __launch_bounds__(256) k_up(const float* __restrict__ hid,
                                            const float* __restrict__ Wu,
                                            const float* __restrict__ rsw,
                                            float* __restrict__ out) {
    const int u0 = blockIdx.x * 128;
    __shared__ float a_sm[128 * 33];
    __shared__ float w_sm[128 * 33];
    const int tid = threadIdx.x;
    const int rg = tid & 15;
    const int cg = tid >> 4;
    float acc[8][8];
#pragma unroll
    for (int i = 0; i < 8; i++)
#pragma unroll
        for (int j = 0; j < 8; j++) acc[i][j] = 0.f;

    for (int kc = 0; kc < 64; kc += 32) {
        __syncthreads();
        for (int i = tid; i < 128 * 32; i += 256) {
            int r = i >> 5, kk = i & 31;
            a_sm[r * 33 + kk] = g_mo[(size_t)(u0 + r) * SDIM + kc + kk];
        }
        for (int i = tid; i < 128 * 32; i += 256) {
            int c = i >> 5, kk = i & 31;
            w_sm[c * 33 + kk] = Wu[(size_t)c * SDIM + kc + kk];
        }
        __syncthreads();
#pragma unroll 2
        for (int kk = 0; kk < 32; kk++) {
            float av[8], wv[8];
#pragma unroll
            for (int rr = 0; rr < 8; rr++) av[rr] = a_sm[(rg + 16 * rr) * 33 + kk];
#pragma unroll
            for (int cc = 0; cc < 8; cc++) wv[cc] = w_sm[(cg * 8 + cc) * 33 + kk];
#pragma unroll
            for (int rr = 0; rr < 8; rr++)
#pragma unroll
                for (int cc = 0; cc < 8; cc++)
                    acc[rr][cc] = fmaf(av[rr], wv[cc], acc[rr][cc]);
        }
    }
    const float rw = rsw[0];
#pragma unroll
    for (int rr = 0; rr < 8; rr++) {
        size_t b = (size_t)(u0 + rg + 16 * rr) * HDIM + cg * 8;
        float4 h0 = *(const float4*)&hid[b];
        float4 h1 = *(const float4*)&hid[b + 4];
        float4 o0 = make_float4(fmaf(rw, acc[rr][0], h0.x), fmaf(rw, acc[rr][1], h0.y),
                                fmaf(rw, acc[rr][2], h0.z), fmaf(rw, acc[rr][3], h0.w));
        float4 o1 = make_float4(fmaf(rw, acc[rr][4], h1.x), fmaf(rw, acc[rr][5], h1.y),
                                fmaf(rw, acc[rr][6], h1.z), fmaf(rw, acc[rr][7], h1.w));
        *(float4*)&out[b] = o0;
        *(float4*)&out[b + 4] = o1;
    }
}

extern "C" void kernel_launch(void* const* d_in, const int* in_sizes, int n_in,
                              void* d_out, int out_size) {
    const float* hid = (const float*)d_in[0];
    const float* stk = (const float*)d_in[1];
    const float* msk = (const float*)d_in[2];
    const float* Wa  = (const float*)d_in[3];
    const float* Wg  = (const float*)d_in[4];
    const float* Wd  = (const float*)d_in[5];
    const float* Wu  = (const float*)d_in[6];
    const float* rsw = (const float*)d_in[7];
    float* out = (float*)d_out;

    k_logits<<<512, 256>>>(hid, Wa);
    k_actsm<<<256, 256>>>();
    k_down<<<512, 256>>>(hid, Wd);
    k_stack<<<16384, 256>>>(stk, msk, Wg, out);
    k_up<<<512, 256>>>(hid, Wu, rsw, out);
}

// round 3
// speedup vs baseline: 1.0217x; 1.0217x over previous
#include <cuda_runtime.h>

#define NTOK   4096
#define DMODEL 2048
#define NH     16
#define HDIM   128
#define SDIM   64
#define NSLOT  16
#define NUNIT  (NTOK * NH)

#define OUT_STACK_OFF 8388608ll
#define OUT_MASK_OFF  75497472ll

__device__ float g_part[8ll * NTOK * 48];
__device__ float g_act[(size_t)NTOK * 48];
__device__ float g_k[(size_t)NUNIT * SDIM];
__device__ float g_mo[(size_t)NUNIT * SDIM];

// ---- Kernel 1: logits partials (split-K). grid = 64 token-tiles * 8 ksplits.
__global__ void __launch_bounds__(256) k_logits(const float* __restrict__ hid,
                                                const float* __restrict__ Wa) {
    const int tile = blockIdx.x >> 3;
    const int ks   = blockIdx.x & 7;
    const int t0   = tile * 64;
    const int kb   = ks * 256;
    __shared__ float a_sm[64 * 65];
    __shared__ float w_sm[48 * 65];
    const int tid = threadIdx.x;
    const int tg  = tid & 15;
    const int og  = tid >> 4;
    float acc[4][3];
#pragma unroll
    for (int i = 0; i < 4; i++)
#pragma unroll
        for (int j = 0; j < 3; j++) acc[i][j] = 0.f;

    for (int kc = 0; kc < 256; kc += 64) {
        __syncthreads();
        for (int i = tid; i < 64 * 64; i += 256) {
            int t = i >> 6, kk = i & 63;
            a_sm[t * 65 + kk] = hid[(size_t)(t0 + t) * DMODEL + kb + kc + kk];
        }
        for (int i = tid; i < 48 * 64; i += 256) {
            int o = i >> 6, kk = i & 63;
            w_sm[o * 65 + kk] = Wa[(size_t)o * DMODEL + kb + kc + kk];
        }
        __syncthreads();
#pragma unroll 4
        for (int kk = 0; kk < 64; kk++) {
            float av[4], wv[3];
#pragma unroll
            for (int tt = 0; tt < 4; tt++) av[tt] = a_sm[(tg + 16 * tt) * 65 + kk];
#pragma unroll
            for (int oc = 0; oc < 3; oc++) wv[oc] = w_sm[(og * 3 + oc) * 65 + kk];
#pragma unroll
            for (int tt = 0; tt < 4; tt++)
#pragma unroll
                for (int oc = 0; oc < 3; oc++)
                    acc[tt][oc] = fmaf(av[tt], wv[oc], acc[tt][oc]);
        }
    }
#pragma unroll
    for (int tt = 0; tt < 4; tt++)
#pragma unroll
        for (int oc = 0; oc < 3; oc++)
            g_part[((size_t)ks * NTOK + t0 + tg + 16 * tt) * 48 + og * 3 + oc] =
                acc[tt][oc];
}

// ---- Kernel 2: reduce partials, softmax over 3 actions.
__global__ void __launch_bounds__(256) k_actsm() {
    const int gid = blockIdx.x * 256 + threadIdx.x;  // 0..65535
    const int t = gid >> 4, h = gid & 15;
    float l0 = 0.f, l1 = 0.f, l2 = 0.f;
#pragma unroll
    for (int ks = 0; ks < 8; ks++) {
        size_t b = ((size_t)ks * NTOK + t) * 48 + h * 3;
        l0 += g_part[b]; l1 += g_part[b + 1]; l2 += g_part[b + 2];
    }
    const float s = 0.08838834764831845f;  // 1/sqrt(128)
    l0 *= s; l1 *= s; l2 *= s;
    float m = fmaxf(l0, fmaxf(l1, l2));
    float e0 = __expf(l0 - m), e1 = __expf(l1 - m), e2 = __expf(l2 - m);
    float inv = 1.f / (e0 + e1 + e2);
    size_t ob = (size_t)t * 48 + h * 3;
    g_act[ob] = e0 * inv; g_act[ob + 1] = e1 * inv; g_act[ob + 2] = e2 * inv;
}

// ---- Kernel 3: k = hidden([65536 x 128]) @ W_down^T -> [65536 x 64].
__global__ void __launch_bounds__(256) k_down(const float* __restrict__ hid,
                                              const float* __restrict__ Wd) {
    const int u0 = blockIdx.x * 128;
    __shared__ float a_sm[128 * 33];
    __shared__ float w_sm[64 * 33];
    const int tid = threadIdx.x;
    const int rg = tid & 15;
    const int cg = tid >> 4;
    float acc[8][4];
#pragma unroll
    for (int i = 0; i < 8; i++)
#pragma unroll
        for (int j = 0; j < 4; j++) acc[i][j] = 0.f;

    for (int kc = 0; kc < 128; kc += 32) {
        __syncthreads();
        for (int i = tid; i < 128 * 32; i += 256) {
            int r = i >> 5, kk = i & 31;
            a_sm[r * 33 + kk] = hid[(size_t)(u0 + r) * HDIM + kc + kk];
        }
        for (int i = tid; i < 64 * 32; i += 256) {
            int c = i >> 5, kk = i & 31;
            w_sm[c * 33 + kk] = Wd[(size_t)c * HDIM + kc + kk];
        }
        __syncthreads();
#pragma unroll 4
        for (int kk = 0; kk < 32; kk++) {
            float av[8], wv[4];
#pragma unroll
            for (int rr = 0; rr < 8; rr++) av[rr] = a_sm[(rg + 16 * rr) * 33 + kk];
#pragma unroll
            for (int cc = 0; cc < 4; cc++) wv[cc] = w_sm[(cg * 4 + cc) * 33 + kk];
#pragma unroll
            for (int rr = 0; rr < 8; rr++)
#pragma unroll
                for (int cc = 0; cc < 4; cc++)
                    acc[rr][cc] = fmaf(av[rr], wv[cc], acc[rr][cc]);
        }
    }
#pragma unroll
    for (int rr = 0; rr < 8; rr++) {
        float4 v = make_float4(acc[rr][0], acc[rr][1], acc[rr][2], acc[rr][3]);
        *(float4*)&g_k[(size_t)(u0 + rg + 16 * rr) * SDIM + cg * 4] = v;
    }
}

// ---- Kernel 4: stack blend + masked gate softmax + memory_output scratch.
// 4 units/block, 256 threads. float4 staged via smem, in-place blend.
__global__ void __launch_bounds__(256) k_stack(const float* __restrict__ stk,
                                               const float* __restrict__ msk,
                                               const float* __restrict__ Wg,
                                               float* __restrict__ out) {
    __shared__ float s[4 * NSLOT * SDIM];   // 16KB: [unit][slot][d]
    __shared__ float msm[4][17];
    __shared__ float red[4][2][16];
    const int tid = threadIdx.x;
    const int uu  = tid >> 6;
    const int d   = tid & 63;
    const int u0  = blockIdx.x * 4;
    const int u   = u0 + uu;
    const int t   = u >> 4, h = u & 15;

    // cooperative float4 load of 4 units' stacks (4096 floats)
    const float4* gsrc = (const float4*)(stk + (size_t)u0 * (NSLOT * SDIM));
    float4* s4 = (float4*)s;
#pragma unroll
    for (int i = 0; i < 4; i++) s4[tid + 256 * i] = gsrc[tid + 256 * i];

    if (d < 16) msm[uu][d] = msk[(size_t)u * 16 + d];

    size_t ab = (size_t)t * 48 + h * 3;
    const float ap   = g_act[ab];
    const float apop = g_act[ab + 1];
    const float an   = g_act[ab + 2];
    const float kd = g_k[(size_t)u * 64 + d];
    const float gd = Wg[d];
    __syncthreads();

    float* su = s + uu * (NSLOT * SDIM);
    const int lane = tid & 31;
    const int wh   = (tid >> 5) & 1;

    // rolling in-place blend + gate-score partial reductions
    float prev = kd;                       // push source for slot 0
    float cur  = su[0 * 64 + d];
    float nxt  = su[1 * 64 + d];
#pragma unroll
    for (int j = 0; j < 16; j++) {
        float nw = ap * prev + apop * nxt + an * cur;
        su[j * 64 + d] = nw;
        float v = nw * gd;
        v += __shfl_xor_sync(0xffffffffu, v, 16);
        v += __shfl_xor_sync(0xffffffffu, v, 8);
        v += __shfl_xor_sync(0xffffffffu, v, 4);
        v += __shfl_xor_sync(0xffffffffu, v, 2);
        v += __shfl_xor_sync(0xffffffffu, v, 1);
        if (lane == 0) red[uu][wh][j] = v;
        prev = cur;
        cur  = nxt;
        nxt  = (j < 14) ? su[(j + 2) * 64 + d] : 0.f;
    }
    __syncthreads();

    // cooperative float4 store of new_stack (issue early, overlap with math)
    float4* gdst = (float4*)(out + OUT_STACK_OFF + (size_t)u0 * (NSLOT * SDIM));
#pragma unroll
    for (int i = 0; i < 4; i++) gdst[tid + 256 * i] = s4[tid + 256 * i];

    // masked softmax over slots (redundant per-thread across d)
    float sc[16], mx = -3.4e38f;
#pragma unroll
    for (int j = 0; j < 16; j++) {
        float pm = (j == 0) ? 1.f : msm[uu][j - 1];
        float qm = (j < 15) ? msm[uu][j + 1] : 0.f;
        float mk = ap * pm + apop * qm + an * msm[uu][j];
        float v = red[uu][0][j] + red[uu][1][j] + (1.f - mk) * (-1e9f);
        sc[j] = v;
        mx = fmaxf(mx, v);
    }
    float ssum = 0.f;
#pragma unroll
    for (int j = 0; j < 16; j++) { sc[j] = __expf(sc[j] - mx); ssum += sc[j]; }
    float inv = 1.f / ssum;

    float mo = 0.f;
#pragma unroll
    for (int j = 0; j < 16; j++) mo += su[j * 64 + d] * sc[j];
    g_mo[(size_t)u * 64 + d] = mo * inv;

    // new mask output
    if (d < 16) {
        int j = d;
        float pm = (j == 0) ? 1.f : msm[uu][j - 1];
        float qm = (j < 15) ? msm[uu][j + 1] : 0.f;
        out[OUT_MASK_OFF + (size_t)u * 16 + j] =
            ap * pm + apop * qm + an * msm[uu][j];
    }
}

// ---- Kernel 5: out = res_weight * (mo @ W_up^T) + hidden.
// 64-row x 128-col tile, 4x8 frag -> 32 accs, ~50 regs.
__global__ void __launch_bounds__(256) k_up(const float* __restrict__ hid,
                                            const float* __restrict__ Wu,
                                            const float* __restrict__ rsw,
                                            float* __restrict__ out) {
    const int u0 = blockIdx.x * 64;
    __shared__ float a_sm[64 * 33];
    __shared__ float w_sm[128 * 33];
    const int tid = threadIdx.x;
    const int rg = tid & 15;   // rows rg + 16*rr (rr<4)
    const int cg = tid >> 4;   // cols cg*8 .. cg*8+7
    float acc[4][8];
#pragma unroll
    for (int i = 0; i < 4; i++)
#pragma unroll
        for (int j = 0; j < 8; j++) acc[i][j] = 0.f;

    for (int kc = 0; kc < 64; kc += 32) {
        __syncthreads();
        for (int i = tid; i < 64 * 32; i += 256) {
            int r = i >> 5, kk = i & 31;
            a_sm[r * 33 + kk] = g_mo[(size_t)(u0 + r) * SDIM + kc + kk];
        }
        for (int i = tid; i < 128 * 32; i += 256) {
            int c = i >> 5, kk = i & 31;
            w_sm[c * 33 + kk] = Wu[(size_t)c * SDIM + kc + kk];
        }
        __syncthreads();
#pragma unroll 4
        for (int kk = 0; kk < 32; kk++) {
            float av[4], wv[8];
#pragma unroll
            for (int rr = 0; rr < 4; rr++) av[rr] = a_sm[(rg + 16 * rr) * 33 + kk];
#pragma unroll
            for (int cc = 0; cc < 8; cc++) wv[cc] = w_sm[(cg * 8 + cc) * 33 + kk];
#pragma unroll
            for (int rr = 0; rr < 4; rr++)
#pragma unroll
                for (int cc = 0; cc < 8; cc++)
                    acc[rr][cc] = fmaf(av[rr], wv[cc], acc[rr][cc]);
        }
    }
    const float rw = rsw[0];
#pragma unroll
    for (int rr = 0; rr < 4; rr++) {
        size_t b = (size_t)(u0 + rg + 16 * rr) * HDIM + cg * 8;
        float4 h0 = *(const float4*)&hid[b];
        float4 h1 = *(const float4*)&hid[b + 4];
        float4 o0 = make_float4(fmaf(rw, acc[rr][0], h0.x), fmaf(rw, acc[rr][1], h0.y),
                                fmaf(rw, acc[rr][2], h0.z), fmaf(rw, acc[rr][3], h0.w));
        float4 o1 = make_float4(fmaf(rw, acc[rr][4], h1.x), fmaf(rw, acc[rr][5], h1.y),
                                fmaf(rw, acc[rr][6], h1.z), fmaf(rw, acc[rr][7], h1.w));
        *(float4*)&out[b] = o0;
        *(float4*)&out[b + 4] = o1;
    }
}

extern "C" void kernel_launch(void* const* d_in, const int* in_sizes, int n_in,
                              void* d_out, int out_size) {
    const float* hid = (const float*)d_in[0];
    const float* stk = (const float*)d_in[1];
    const float* msk = (const float*)d_in[2];
    const float* Wa  = (const float*)d_in[3];
    const float* Wg  = (const float*)d_in[4];
    const float* Wd  = (const float*)d_in[5];
    const float* Wu  = (const float*)d_in[6];
    const float* rsw = (const float*)d_in[7];
    float* out = (float*)d_out;

    k_logits<<<512, 256>>>(hid, Wa);
    k_actsm<<<256, 256>>>();
    k_down<<<512, 256>>>(hid, Wd);
    k_stack<<<16384, 256>>>(stk, msk, Wg, out);
    k_up<<<1024, 256>>>(hid, Wu, rsw, out);
}

// round 4
// speedup vs baseline: 1.1379x; 1.1137x over previous
#include <cuda_runtime.h>

#define NTOK   4096
#define DMODEL 2048
#define NH     16
#define HDIM   128
#define SDIM   64
#define NSLOT  16
#define NUNIT  (NTOK * NH)

#define OUT_STACK_OFF 8388608ll
#define OUT_MASK_OFF  75497472ll

__device__ float g_part[8ll * NTOK * 48];
__device__ float g_act[(size_t)NTOK * 48];
__device__ float g_k[(size_t)NUNIT * SDIM];
__device__ float g_mo[(size_t)NUNIT * SDIM];

// ---- Kernel 1: logits partials (split-K). grid = 64 token-tiles * 8 ksplits.
__global__ void __launch_bounds__(256) k_logits(const float* __restrict__ hid,
                                                const float* __restrict__ Wa) {
    const int tile = blockIdx.x >> 3;
    const int ks   = blockIdx.x & 7;
    const int t0   = tile * 64;
    const int kb   = ks * 256;
    __shared__ float a_sm[64 * 68];
    __shared__ float w_sm[48 * 68];
    const int tid = threadIdx.x;
    const int tg  = tid & 15;
    const int og  = tid >> 4;
    float acc[4][3];
#pragma unroll
    for (int i = 0; i < 4; i++)
#pragma unroll
        for (int j = 0; j < 3; j++) acc[i][j] = 0.f;

    for (int kc = 0; kc < 256; kc += 64) {
        __syncthreads();
        for (int i = tid; i < 64 * 64; i += 256) {
            int t = i >> 6, kk = i & 63;
            a_sm[t * 68 + kk] = hid[(size_t)(t0 + t) * DMODEL + kb + kc + kk];
        }
        for (int i = tid; i < 48 * 64; i += 256) {
            int o = i >> 6, kk = i & 63;
            w_sm[o * 68 + kk] = Wa[(size_t)o * DMODEL + kb + kc + kk];
        }
        __syncthreads();
#pragma unroll
        for (int kk = 0; kk < 64; kk += 4) {
            float4 av[4], wv[3];
#pragma unroll
            for (int tt = 0; tt < 4; tt++)
                av[tt] = *(const float4*)&a_sm[(tg + 16 * tt) * 68 + kk];
#pragma unroll
            for (int oc = 0; oc < 3; oc++)
                wv[oc] = *(const float4*)&w_sm[(og * 3 + oc) * 68 + kk];
#pragma unroll
            for (int tt = 0; tt < 4; tt++)
#pragma unroll
                for (int oc = 0; oc < 3; oc++) {
                    acc[tt][oc] = fmaf(av[tt].x, wv[oc].x, acc[tt][oc]);
                    acc[tt][oc] = fmaf(av[tt].y, wv[oc].y, acc[tt][oc]);
                    acc[tt][oc] = fmaf(av[tt].z, wv[oc].z, acc[tt][oc]);
                    acc[tt][oc] = fmaf(av[tt].w, wv[oc].w, acc[tt][oc]);
                }
        }
    }
#pragma unroll
    for (int tt = 0; tt < 4; tt++)
#pragma unroll
        for (int oc = 0; oc < 3; oc++)
            g_part[((size_t)ks * NTOK + t0 + tg + 16 * tt) * 48 + og * 3 + oc] =
                acc[tt][oc];
}

// ---- Kernel 2: reduce partials, softmax over 3 actions.
__global__ void __launch_bounds__(256) k_actsm() {
    const int gid = blockIdx.x * 256 + threadIdx.x;
    const int t = gid >> 4, h = gid & 15;
    float l0 = 0.f, l1 = 0.f, l2 = 0.f;
#pragma unroll
    for (int ks = 0; ks < 8; ks++) {
        size_t b = ((size_t)ks * NTOK + t) * 48 + h * 3;
        l0 += g_part[b]; l1 += g_part[b + 1]; l2 += g_part[b + 2];
    }
    const float s = 0.08838834764831845f;
    l0 *= s; l1 *= s; l2 *= s;
    float m = fmaxf(l0, fmaxf(l1, l2));
    float e0 = __expf(l0 - m), e1 = __expf(l1 - m), e2 = __expf(l2 - m);
    float inv = 1.f / (e0 + e1 + e2);
    size_t ob = (size_t)t * 48 + h * 3;
    g_act[ob] = e0 * inv; g_act[ob + 1] = e1 * inv; g_act[ob + 2] = e2 * inv;
}

// ---- Kernel 3: k = hidden([65536 x 128]) @ W_down^T -> [65536 x 64].
__global__ void __launch_bounds__(256) k_down(const float* __restrict__ hid,
                                              const float* __restrict__ Wd) {
    const int u0 = blockIdx.x * 128;
    __shared__ float a_sm[128 * 36];
    __shared__ float w_sm[64 * 36];
    const int tid = threadIdx.x;
    const int rg = tid & 15;
    const int cg = tid >> 4;
    float acc[8][4];
#pragma unroll
    for (int i = 0; i < 8; i++)
#pragma unroll
        for (int j = 0; j < 4; j++) acc[i][j] = 0.f;

    for (int kc = 0; kc < 128; kc += 32) {
        __syncthreads();
        for (int i = tid; i < 128 * 32; i += 256) {
            int r = i >> 5, kk = i & 31;
            a_sm[r * 36 + kk] = hid[(size_t)(u0 + r) * HDIM + kc + kk];
        }
        for (int i = tid; i < 64 * 32; i += 256) {
            int c = i >> 5, kk = i & 31;
            w_sm[c * 36 + kk] = Wd[(size_t)c * HDIM + kc + kk];
        }
        __syncthreads();
#pragma unroll
        for (int kk = 0; kk < 32; kk += 4) {
            float4 av[8], wv[4];
#pragma unroll
            for (int rr = 0; rr < 8; rr++)
                av[rr] = *(const float4*)&a_sm[(rg + 16 * rr) * 36 + kk];
#pragma unroll
            for (int cc = 0; cc < 4; cc++)
                wv[cc] = *(const float4*)&w_sm[(cg * 4 + cc) * 36 + kk];
#pragma unroll
            for (int rr = 0; rr < 8; rr++)
#pragma unroll
                for (int cc = 0; cc < 4; cc++) {
                    acc[rr][cc] = fmaf(av[rr].x, wv[cc].x, acc[rr][cc]);
                    acc[rr][cc] = fmaf(av[rr].y, wv[cc].y, acc[rr][cc]);
                    acc[rr][cc] = fmaf(av[rr].z, wv[cc].z, acc[rr][cc]);
                    acc[rr][cc] = fmaf(av[rr].w, wv[cc].w, acc[rr][cc]);
                }
        }
    }
#pragma unroll
    for (int rr = 0; rr < 8; rr++) {
        float4 v = make_float4(acc[rr][0], acc[rr][1], acc[rr][2], acc[rr][3]);
        *(float4*)&g_k[(size_t)(u0 + rg + 16 * rr) * SDIM + cg * 4] = v;
    }
}

// ---- Kernel 4: stack blend via linearity. 4 units/block, all-float4.
__global__ void __launch_bounds__(256) k_stack(const float* __restrict__ stk,
                                               const float* __restrict__ msk,
                                               const float* __restrict__ Wg,
                                               float* __restrict__ out) {
    __shared__ float4 s4[4 * 256];      // [unit][slot][dv]
    __shared__ float red[4][17];        // S_j per unit, [16]=dot(k,g)
    __shared__ float msm[64];
    __shared__ float acts[12];
    const int tid  = threadIdx.x;
    const int slot = tid >> 4;
    const int dv   = tid & 15;
    const int u0   = blockIdx.x * 4;

    if (tid < 64) msm[tid] = msk[(size_t)u0 * 16 + tid];
    if (tid < 12) {
        int i = tid / 3, c = tid - i * 3;
        int u = u0 + i;
        acts[tid] = g_act[(size_t)(u >> 4) * 48 + (u & 15) * 3 + c];
    }
    const float4 g4 = ((const float4*)Wg)[dv];
    const float4* gs = (const float4*)stk + (size_t)u0 * 256;
    float4 r4[4];
#pragma unroll
    for (int i = 0; i < 4; i++) { r4[i] = gs[tid + 256 * i]; s4[tid + 256 * i] = r4[i]; }
    float4 k4[4];
    if (slot == 0) {
#pragma unroll
        for (int i = 0; i < 4; i++)
            k4[i] = ((const float4*)g_k)[(size_t)(u0 + i) * 16 + dv];
    }

    // S_j = dot(old row, g): reduce over dv (16-lane groups)
#pragma unroll
    for (int i = 0; i < 4; i++) {
        float p = r4[i].x * g4.x + r4[i].y * g4.y + r4[i].z * g4.z + r4[i].w * g4.w;
        p += __shfl_xor_sync(0xffffffffu, p, 8);
        p += __shfl_xor_sync(0xffffffffu, p, 4);
        p += __shfl_xor_sync(0xffffffffu, p, 2);
        p += __shfl_xor_sync(0xffffffffu, p, 1);
        if (dv == 0) red[i][slot] = p;
    }
    if (slot == 0) {
#pragma unroll
        for (int i = 0; i < 4; i++) {
            float p = k4[i].x * g4.x + k4[i].y * g4.y + k4[i].z * g4.z + k4[i].w * g4.w;
            p += __shfl_xor_sync(0x0000ffffu, p, 8);
            p += __shfl_xor_sync(0x0000ffffu, p, 4);
            p += __shfl_xor_sync(0x0000ffffu, p, 2);
            p += __shfl_xor_sync(0x0000ffffu, p, 1);
            if (dv == 0) red[i][16] = p;
        }
    }
    __syncthreads();

    // blend -> new_stack, straight to gmem
    float4* os = (float4*)(out + OUT_STACK_OFF) + (size_t)u0 * 256;
#pragma unroll
    for (int i = 0; i < 4; i++) {
        float ap = acts[i * 3], apop = acts[i * 3 + 1], an = acts[i * 3 + 2];
        float4 prev = (slot == 0) ? k4[i] : s4[i * 256 + tid - 16];
        float4 nxt  = (slot == 15) ? make_float4(0.f, 0.f, 0.f, 0.f)
                                   : s4[i * 256 + tid + 16];
        float4 c = r4[i];
        float4 nw;
        nw.x = ap * prev.x + apop * nxt.x + an * c.x;
        nw.y = ap * prev.y + apop * nxt.y + an * c.y;
        nw.z = ap * prev.z + apop * nxt.z + an * c.z;
        nw.w = ap * prev.w + apop * nxt.w + an * c.w;
        os[i * 256 + tid] = nw;
    }

    // tail: 64 threads (unit q, float4-chunk x): mask, softmax, mo
    if (tid < 64) {
        const int q = tid >> 4, x = tid & 15;
        float ap = acts[q * 3], apop = acts[q * 3 + 1], an = acts[q * 3 + 2];
        float mk[16];
#pragma unroll
        for (int j = 0; j < 16; j++) {
            float pm = (j == 0) ? 1.f : msm[q * 16 + j - 1];
            float qm = (j < 15) ? msm[q * 16 + j + 1] : 0.f;
            mk[j] = ap * pm + apop * qm + an * msm[q * 16 + j];
        }
        out[OUT_MASK_OFF + (size_t)u0 * 16 + tid] = mk[x];

        float kdot = red[q][16];
        float sc[16], mx = -3.4e38f;
#pragma unroll
        for (int j = 0; j < 16; j++) {
            float Sm1 = (j == 0) ? kdot : red[q][j - 1];
            float Sp1 = (j < 15) ? red[q][j + 1] : 0.f;
            float v = ap * Sm1 + apop * Sp1 + an * red[q][j] + (1.f - mk[j]) * (-1e9f);
            sc[j] = v;
            mx = fmaxf(mx, v);
        }
        float ss = 0.f;
#pragma unroll
        for (int j = 0; j < 16; j++) { sc[j] = __expf(sc[j] - mx); ss += sc[j]; }
        float inv = 1.f / ss;

        // mo = c_{-1}*k + sum_m c_m * old_m   (c from softmax weights)
        float4 kq = ((const float4*)g_k)[(size_t)(u0 + q) * 16 + x];
        float cm1 = ap * sc[0] * inv;
        float4 mo;
        mo.x = cm1 * kq.x; mo.y = cm1 * kq.y; mo.z = cm1 * kq.z; mo.w = cm1 * kq.w;
#pragma unroll
        for (int m = 0; m < 16; m++) {
            float wp1 = (m < 15) ? sc[m + 1] : 0.f;
            float wm1 = (m > 0) ? sc[m - 1] : 0.f;
            float cm = (ap * wp1 + apop * wm1 + an * sc[m]) * inv;
            float4 row = s4[q * 256 + m * 16 + x];
            mo.x = fmaf(cm, row.x, mo.x);
            mo.y = fmaf(cm, row.y, mo.y);
            mo.z = fmaf(cm, row.z, mo.z);
            mo.w = fmaf(cm, row.w, mo.w);
        }
        ((float4*)g_mo)[(size_t)(u0 + q) * 16 + x] = mo;
    }
}

// ---- Kernel 5: out = res_weight * (mo @ W_up^T) + hidden. 64x128 tile, 4x8 frag.
__global__ void __launch_bounds__(256) k_up(const float* __restrict__ hid,
                                            const float* __restrict__ Wu,
                                            const float* __restrict__ rsw,
                                            float* __restrict__ out) {
    const int u0 = blockIdx.x * 64;
    __shared__ float a_sm[64 * 36];
    __shared__ float w_sm[128 * 36];
    const int tid = threadIdx.x;
    const int rg = tid & 15;
    const int cg = tid >> 4;
    float acc[4][8];
#pragma unroll
    for (int i = 0; i < 4; i++)
#pragma unroll
        for (int j = 0; j < 8; j++) acc[i][j] = 0.f;

    for (int kc = 0; kc < 64; kc += 32) {
        __syncthreads();
        for (int i = tid; i < 64 * 32; i += 256) {
            int r = i >> 5, kk = i & 31;
            a_sm[r * 36 + kk] = g_mo[(size_t)(u0 + r) * SDIM + kc + kk];
        }
        for (int i = tid; i < 128 * 32; i += 256) {
            int c = i >> 5, kk = i & 31;
            w_sm[c * 36 + kk] = Wu[(size_t)c * SDIM + kc + kk];
        }
        __syncthreads();
#pragma unroll
        for (int kk = 0; kk < 32; kk += 4) {
            float4 av[4], wv[8];
#pragma unroll
            for (int rr = 0; rr < 4; rr++)
                av[rr] = *(const float4*)&a_sm[(rg + 16 * rr) * 36 + kk];
#pragma unroll
            for (int cc = 0; cc < 8; cc++)
                wv[cc] = *(const float4*)&w_sm[(cg * 8 + cc) * 36 + kk];
#pragma unroll
            for (int rr = 0; rr < 4; rr++)
#pragma unroll
                for (int cc = 0; cc < 8; cc++) {
                    acc[rr][cc] = fmaf(av[rr].x, wv[cc].x, acc[rr][cc]);
                    acc[rr][cc] = fmaf(av[rr].y, wv[cc].y, acc[rr][cc]);
                    acc[rr][cc] = fmaf(av[rr].z, wv[cc].z, acc[rr][cc]);
                    acc[rr][cc] = fmaf(av[rr].w, wv[cc].w, acc[rr][cc]);
                }
        }
    }
    const float rw = rsw[0];
#pragma unroll
    for (int rr = 0; rr < 4; rr++) {
        size_t b = (size_t)(u0 + rg + 16 * rr) * HDIM + cg * 8;
        float4 h0 = *(const float4*)&hid[b];
        float4 h1 = *(const float4*)&hid[b + 4];
        float4 o0 = make_float4(fmaf(rw, acc[rr][0], h0.x), fmaf(rw, acc[rr][1], h0.y),
                                fmaf(rw, acc[rr][2], h0.z), fmaf(rw, acc[rr][3], h0.w));
        float4 o1 = make_float4(fmaf(rw, acc[rr][4], h1.x), fmaf(rw, acc[rr][5], h1.y),
                                fmaf(rw, acc[rr][6], h1.z), fmaf(rw, acc[rr][7], h1.w));
        *(float4*)&out[b] = o0;
        *(float4*)&out[b + 4] = o1;
    }
}

extern "C" void kernel_launch(void* const* d_in, const int* in_sizes, int n_in,
                              void* d_out, int out_size) {
    const float* hid = (const float*)d_in[0];
    const float* stk = (const float*)d_in[1];
    const float* msk = (const float*)d_in[2];
    const float* Wa  = (const float*)d_in[3];
    const float* Wg  = (const float*)d_in[4];
    const float* Wd  = (const float*)d_in[5];
    const float* Wu  = (const float*)d_in[6];
    const float* rsw = (const float*)d_in[7];
    float* out = (float*)d_out;

    k_logits<<<512, 256>>>(hid, Wa);
    k_actsm<<<256, 256>>>();
    k_down<<<512, 256>>>(hid, Wd);
    k_stack<<<16384, 256>>>(stk, msk, Wg, out);
    k_up<<<1024, 256>>>(hid, Wu, rsw, out);
}